// round 7
// baseline (speedup 1.0000x reference)
#include <cuda_runtime.h>
#include <cstdint>
#include <math.h>

#define D_MODEL 1024
#define NHEAD   16
#define DK      64
#define BATCH   2
#define NQ      2048
#define NKV     2048

// Scratch (allocation-free)
__device__ float g_Q[BATCH * NQ * D_MODEL];
__device__ float g_attn[BATCH * NQ * D_MODEL];
__device__ float g_vred[BATCH * NHEAD * DK];

// ----------------------------------------------------------------------------
// Fast exp on the FMA/ALU pipes (no MUFU). Handles -1e9 (mask) -> ~0.
// ----------------------------------------------------------------------------
__device__ __forceinline__ float fexp(float x) {
    float y = x * 1.4426950408889634f;
    y = fmaxf(y, -126.0f);
    float t = y + 12582912.0f;
    float n = t - 12582912.0f;
    float f = y - n;
    float p = 1.3333558e-3f;
    p = fmaf(p, f, 9.6181290e-3f);
    p = fmaf(p, f, 5.5504109e-2f);
    p = fmaf(p, f, 2.4022651e-1f);
    p = fmaf(p, f, 6.9314718e-1f);
    p = fmaf(p, f, 1.0f);
    int e = __float_as_int(t) - 0x4B400000;
    float s = __int_as_float((e + 127) << 23);
    return p * s;
}

__device__ __forceinline__ float to_tf32(float x) {
    float r; asm("cvt.rna.tf32.f32 %0, %1;" : "=f"(r) : "f"(x));
    return r;
}
__device__ __forceinline__ uint32_t tf32u(float x) {
    return __float_as_uint(to_tf32(x));
}

__device__ __forceinline__ void mma_tf32(float* c, const uint32_t* a,
                                         uint32_t b0, uint32_t b1) {
    asm volatile(
        "mma.sync.aligned.m16n8k8.row.col.f32.tf32.tf32.f32 "
        "{%0,%1,%2,%3},{%4,%5,%6,%7},{%8,%9},{%0,%1,%2,%3};"
        : "+f"(c[0]), "+f"(c[1]), "+f"(c[2]), "+f"(c[3])
        : "r"(a[0]), "r"(a[1]), "r"(a[2]), "r"(a[3]), "r"(b0), "r"(b1));
}

__device__ __forceinline__ void cp16(void* smem_dst, const void* gmem_src) {
    unsigned s = (unsigned)__cvta_generic_to_shared(smem_dst);
    asm volatile("cp.async.ca.shared.global [%0], [%1], 16;"
                 :: "r"(s), "l"(__cvta_generic_to_global(gmem_src)) : "memory");
}
#define CP_COMMIT() asm volatile("cp.async.commit_group;" ::: "memory")
#define CP_WAIT1()  asm volatile("cp.async.wait_group 1;"  ::: "memory")
#define CP_WAIT0()  asm volatile("cp.async.wait_group 0;"  ::: "memory")

// ----------------------------------------------------------------------------
// Tensor-core GEMM, tf32x3, cp.async double-buffered.
// C[M,N] = A[M,K] @ B[K,N] row-major. 128x128 tile, K-chunk 16, 8 warps 4x2.
// Smem raw fp32; hi/lo tf32 split at fragment build.
// Strides: As 20 (banks 20g+tg), Bs 136 (banks 8tg+g) -> conflict-free.
// ----------------------------------------------------------------------------
__global__ __launch_bounds__(256, 2) void gemm_tc(const float* __restrict__ A,
                                                  const float* __restrict__ B,
                                                  float* __restrict__ C,
                                                  int M, int N, int K)
{
    __shared__ float As[2][128][20];
    __shared__ float Bs[2][16][136];

    const int tid  = threadIdx.x;
    const int warp = tid >> 5;
    const int lane = tid & 31;
    const int g    = lane >> 2;
    const int tg   = lane & 3;
    const int wm   = (warp & 3) * 32;
    const int wn   = (warp >> 2) * 64;
    const int cRow = blockIdx.y * 128;
    const int cCol = blockIdx.x * 128;

    const int ar  = tid >> 2;         // A rows ar, ar+64
    const int ac4 = (tid & 3) * 4;    // A col (floats)
    const int br  = tid >> 5;         // B rows br, br+8
    const int bc4 = (tid & 31) * 4;   // B col (floats)

    float cacc[2][8][4];
#pragma unroll
    for (int mt = 0; mt < 2; mt++)
#pragma unroll
        for (int nt = 0; nt < 8; nt++)
#pragma unroll
            for (int j = 0; j < 4; j++) cacc[mt][nt][j] = 0.f;

    auto stage = [&](int kc, int buf) {
        const int k0 = kc * 16;
        cp16(&As[buf][ar][ac4],      &A[(size_t)(cRow + ar) * K + k0 + ac4]);
        cp16(&As[buf][ar + 64][ac4], &A[(size_t)(cRow + ar + 64) * K + k0 + ac4]);
        cp16(&Bs[buf][br][bc4],      &B[(size_t)(k0 + br) * N + cCol + bc4]);
        cp16(&Bs[buf][br + 8][bc4],  &B[(size_t)(k0 + br + 8) * N + cCol + bc4]);
        CP_COMMIT();
    };

    const int NC = K / 16;
    stage(0, 0);

    for (int kc = 0; kc < NC; kc++) {
        const int buf = kc & 1;
        if (kc + 1 < NC) { stage(kc + 1, buf ^ 1); CP_WAIT1(); }
        else             { CP_WAIT0(); }
        __syncthreads();

#pragma unroll
        for (int ks = 0; ks < 2; ks++) {
            const int k8 = ks * 8;
            uint32_t ah[2][4], al[2][4];
#pragma unroll
            for (int mt = 0; mt < 2; mt++) {
                int m0 = wm + mt * 16 + g;
                float x0 = As[buf][m0][k8 + tg];
                float x1 = As[buf][m0 + 8][k8 + tg];
                float x2 = As[buf][m0][k8 + tg + 4];
                float x3 = As[buf][m0 + 8][k8 + tg + 4];
                float h;
                h = to_tf32(x0); ah[mt][0] = __float_as_uint(h); al[mt][0] = tf32u(x0 - h);
                h = to_tf32(x1); ah[mt][1] = __float_as_uint(h); al[mt][1] = tf32u(x1 - h);
                h = to_tf32(x2); ah[mt][2] = __float_as_uint(h); al[mt][2] = tf32u(x2 - h);
                h = to_tf32(x3); ah[mt][3] = __float_as_uint(h); al[mt][3] = tf32u(x3 - h);
            }
#pragma unroll
            for (int nt = 0; nt < 8; nt++) {
                int n0 = wn + nt * 8 + g;
                float y0 = Bs[buf][k8 + tg][n0];
                float y1 = Bs[buf][k8 + tg + 4][n0];
                float h0 = to_tf32(y0), h1 = to_tf32(y1);
                uint32_t bh0 = __float_as_uint(h0), bl0 = tf32u(y0 - h0);
                uint32_t bh1 = __float_as_uint(h1), bl1 = tf32u(y1 - h1);
#pragma unroll
                for (int mt = 0; mt < 2; mt++) {
                    mma_tf32(cacc[mt][nt], ah[mt], bh0, bh1);
                    mma_tf32(cacc[mt][nt], ah[mt], bl0, bl1);
                    mma_tf32(cacc[mt][nt], al[mt], bh0, bh1);
                }
            }
        }
        __syncthreads();
    }

#pragma unroll
    for (int mt = 0; mt < 2; mt++) {
        int row0 = cRow + wm + mt * 16 + g;
#pragma unroll
        for (int nt = 0; nt < 8; nt++) {
            int col = cCol + wn + nt * 8 + 2 * tg;
            *(float2*)&C[(size_t)row0 * N + col]       = make_float2(cacc[mt][nt][0], cacc[mt][nt][1]);
            *(float2*)&C[(size_t)(row0 + 8) * N + col] = make_float2(cacc[mt][nt][2], cacc[mt][nt][3]);
        }
    }
}

// ----------------------------------------------------------------------------
// Precompute sum(V) over kv per (b,h,d) for the masked-q fallback rows.
// ----------------------------------------------------------------------------
__global__ __launch_bounds__(256) void vred_kernel(const float* __restrict__ V,
                                                   float* __restrict__ out)
{
    const int bh = blockIdx.x;
    const float* Vb = V + (size_t)bh * NKV * DK;
    const int t  = threadIdx.x;
    const int d4 = (t & 15) * 4;
    const int r0 = t >> 4;
    float4 acc = make_float4(0.f, 0.f, 0.f, 0.f);
    for (int r = r0; r < NKV; r += 16) {
        float4 v = *(const float4*)&Vb[(size_t)r * DK + d4];
        acc.x += v.x; acc.y += v.y; acc.z += v.z; acc.w += v.w;
    }
    __shared__ float red[16][64];
    *(float4*)&red[r0][d4] = acc;
    __syncthreads();
    if (t < 64) {
        float s = 0.f;
#pragma unroll
        for (int i = 0; i < 16; i++) s += red[i][t];
        out[bh * DK + t] = s;
    }
}

// ----------------------------------------------------------------------------
// Tensor-core attention (tf32 mma, exp-without-max), cp.async double-buffered.
// grid (NQ/128, NHEAD, BATCH), 256 threads. KV tile 64.
// ----------------------------------------------------------------------------
struct AttnSmem {
    float    Ks[2][64][68];
    float    Vs[2][64][72];
    uint32_t Ps[128][68];
    float    kvsel[2][64];
    float    sv[64];
};

__global__ __launch_bounds__(256, 2) void attn_mma(
    const float* __restrict__ Q,
    const float* __restrict__ Kin,
    const float* __restrict__ Vin,
    const unsigned* __restrict__ kvmask,
    const unsigned* __restrict__ qmask,
    const float* __restrict__ vred,
    float* __restrict__ attn)
{
    extern __shared__ AttnSmem smem_raw[];
    AttnSmem& s = smem_raw[0];

    const int tid  = threadIdx.x;
    const int warp = tid >> 5;
    const int lane = tid & 31;
    const int g    = lane >> 2;
    const int tg   = lane & 3;
    const int b    = blockIdx.z;
    const int h    = blockIdx.y;
    const int q0   = blockIdx.x * 128;
    const int qb   = warp * 16;

    const float* Kb = Kin + (size_t)(b * NHEAD + h) * NKV * DK;
    const float* Vb = Vin + (size_t)(b * NHEAD + h) * NKV * DK;

    // ---- Q fragments (tf32), resident in regs ----
    uint32_t qf[8][4];
    {
        const float* qp = Q + (size_t)(b * NQ + q0 + qb) * D_MODEL + h * DK;
#pragma unroll
        for (int ks = 0; ks < 8; ks++) {
            qf[ks][0] = tf32u(qp[(size_t)g       * D_MODEL + 8 * ks + tg]);
            qf[ks][1] = tf32u(qp[(size_t)(g + 8) * D_MODEL + 8 * ks + tg]);
            qf[ks][2] = tf32u(qp[(size_t)g       * D_MODEL + 8 * ks + tg + 4]);
            qf[ks][3] = tf32u(qp[(size_t)(g + 8) * D_MODEL + 8 * ks + tg + 4]);
        }
    }

    float of[8][4];
#pragma unroll
    for (int nt = 0; nt < 8; nt++)
#pragma unroll
        for (int j = 0; j < 4; j++) of[nt][j] = 0.f;
    float l0 = 0.f, l1 = 0.f;

    if (tid < 64) s.sv[tid] = vred[(b * NHEAD + h) * DK + tid];

    auto stage = [&](int t, int buf) {
        const int k0 = t * 64;
#pragma unroll
        for (int i = 0; i < 4; i++) {
            int id = tid + i * 256;
            int r = id >> 4, c4 = (id & 15) * 4;
            cp16(&s.Ks[buf][r][c4], &Kb[(size_t)(k0 + r) * DK + c4]);
            cp16(&s.Vs[buf][r][c4], &Vb[(size_t)(k0 + r) * DK + c4]);
        }
        CP_COMMIT();
        if (tid < 64)
            s.kvsel[buf][tid] = (kvmask[b * NKV + k0 + tid] != 0u) ? 0.f : -1e9f;
    };

    const int NT = NKV / 64;
    stage(0, 0);

    for (int t = 0; t < NT; t++) {
        const int buf = t & 1;
        if (t + 1 < NT) { stage(t + 1, buf ^ 1); CP_WAIT1(); }
        else            { CP_WAIT0(); }
        __syncthreads();

        // ---- S = Q K^T ----
        float sc[8][4];
#pragma unroll
        for (int nt = 0; nt < 8; nt++)
#pragma unroll
            for (int j = 0; j < 4; j++) sc[nt][j] = 0.f;
#pragma unroll
        for (int ks = 0; ks < 8; ks++) {
#pragma unroll
            for (int nt = 0; nt < 8; nt++) {
                uint32_t kb0 = tf32u(s.Ks[buf][8 * nt + g][8 * ks + tg]);
                uint32_t kb1 = tf32u(s.Ks[buf][8 * nt + g][8 * ks + tg + 4]);
                mma_tf32(sc[nt], qf[ks], kb0, kb1);
            }
        }

        // ---- epilogue: p = exp(s/8 + sel), accumulate l, store P (tf32) ----
#pragma unroll
        for (int nt = 0; nt < 8; nt++) {
            float s0 = s.kvsel[buf][8 * nt + 2 * tg];
            float s1 = s.kvsel[buf][8 * nt + 2 * tg + 1];
            float p0 = fexp(fmaf(sc[nt][0], 0.125f, s0));
            float p1 = fexp(fmaf(sc[nt][1], 0.125f, s1));
            float p2 = fexp(fmaf(sc[nt][2], 0.125f, s0));
            float p3 = fexp(fmaf(sc[nt][3], 0.125f, s1));
            l0 += p0 + p1;
            l1 += p2 + p3;
            uint2 w0 = make_uint2(tf32u(p0), tf32u(p1));
            uint2 w1 = make_uint2(tf32u(p2), tf32u(p3));
            *(uint2*)&s.Ps[qb + g][8 * nt + 2 * tg]     = w0;
            *(uint2*)&s.Ps[qb + g + 8][8 * nt + 2 * tg] = w1;
        }
        __syncwarp();

        // ---- O += P V ----
#pragma unroll
        for (int ks = 0; ks < 8; ks++) {
            uint32_t pa[4];
            pa[0] = s.Ps[qb + g][8 * ks + tg];
            pa[1] = s.Ps[qb + g + 8][8 * ks + tg];
            pa[2] = s.Ps[qb + g][8 * ks + tg + 4];
            pa[3] = s.Ps[qb + g + 8][8 * ks + tg + 4];
#pragma unroll
            for (int nt = 0; nt < 8; nt++) {
                uint32_t vb0 = tf32u(s.Vs[buf][8 * ks + tg][8 * nt + g]);
                uint32_t vb1 = tf32u(s.Vs[buf][8 * ks + tg + 4][8 * nt + g]);
                mma_tf32(of[nt], pa, vb0, vb1);
            }
        }
        __syncthreads();
    }

    // ---- l reduction and output ----
    l0 += __shfl_xor_sync(0xffffffffu, l0, 1);
    l0 += __shfl_xor_sync(0xffffffffu, l0, 2);
    l1 += __shfl_xor_sync(0xffffffffu, l1, 1);
    l1 += __shfl_xor_sync(0xffffffffu, l1, 2);
    const float inv0 = 1.f / l0;
    const float inv1 = 1.f / l1;
    const bool qok0 = (qmask[b * NQ + q0 + qb + g]     != 0u);
    const bool qok1 = (qmask[b * NQ + q0 + qb + g + 8] != 0u);
    const float u = 1.f / 2048.f;

    float* op0 = attn + (size_t)(b * NQ + q0 + qb + g)     * D_MODEL + h * DK;
    float* op1 = attn + (size_t)(b * NQ + q0 + qb + g + 8) * D_MODEL + h * DK;
#pragma unroll
    for (int nt = 0; nt < 8; nt++) {
        int d = 8 * nt + 2 * tg;
        float2 o0, o1;
        if (qok0) { o0.x = of[nt][0] * inv0; o0.y = of[nt][1] * inv0; }
        else      { o0.x = s.sv[d] * u;      o0.y = s.sv[d + 1] * u; }
        if (qok1) { o1.x = of[nt][2] * inv1; o1.y = of[nt][3] * inv1; }
        else      { o1.x = s.sv[d] * u;      o1.y = s.sv[d + 1] * u; }
        *(float2*)&op0[d] = o0;
        *(float2*)&op1[d] = o1;
    }
}

// ----------------------------------------------------------------------------
// Inputs (metadata order): x, K, V, Wq, Wo, kv_pad_mask, q_pad_mask
// ----------------------------------------------------------------------------
extern "C" void kernel_launch(void* const* d_in, const int* in_sizes, int n_in,
                              void* d_out, int out_size)
{
    const float*    x   = (const float*)d_in[0];
    const float*    K   = (const float*)d_in[1];
    const float*    V   = (const float*)d_in[2];
    const float*    Wq  = (const float*)d_in[3];
    const float*    Wo  = (const float*)d_in[4];
    const unsigned* kvm = (const unsigned*)d_in[5];
    const unsigned* qm  = (const unsigned*)d_in[6];
    float*          out = (float*)d_out;

    float *gQ, *gA, *gV;
    cudaGetSymbolAddress((void**)&gQ, g_Q);
    cudaGetSymbolAddress((void**)&gA, g_attn);
    cudaGetSymbolAddress((void**)&gV, g_vred);

    const int M = BATCH * NQ;
    dim3 gemm_grid(D_MODEL / 128, M / 128);

    const int ATTN_SMEM = (int)sizeof(AttnSmem);
    cudaFuncSetAttribute(attn_mma, cudaFuncAttributeMaxDynamicSharedMemorySize, ATTN_SMEM);

    gemm_tc<<<gemm_grid, 256>>>(x, Wq, gQ, M, D_MODEL, D_MODEL);

    vred_kernel<<<BATCH * NHEAD, 256>>>(V, gV);

    dim3 attn_grid(NQ / 128, NHEAD, BATCH);
    attn_mma<<<attn_grid, 256, ATTN_SMEM>>>(gQ, K, V, kvm, qm, gV, gA);

    gemm_tc<<<gemm_grid, 256>>>(gA, Wo, out, M, D_MODEL, D_MODEL);
}